// round 1
// baseline (speedup 1.0000x reference)
#include <cuda_runtime.h>
#include <math.h>

#define NGRAPH 1024
#define DIM 64
#define INDIM 25
#define MAXN 100000

// ---------------- scratch (device globals; no allocation allowed) ----------
__device__ __align__(16) float g_h0[MAXN * DIM];
__device__ __align__(16) float g_aggr[MAXN * DIM];
__device__ __align__(16) float g_h1[MAXN * DIM];
__device__ float g_e[MAXN];
__device__ int   g_start[NGRAPH + 1];
__device__ float g_hs[NGRAPH * DIM];
__device__ float g_cs[NGRAPH * DIM];
__device__ float g_qstar[NGRAPH * 2 * DIM];
__device__ int   g_is64;

// ---------------- helpers ---------------------------------------------------
__device__ __forceinline__ long long ld_idx(const void* p, long long i, int is64) {
    return is64 ? ((const long long*)p)[i] : (long long)((const int*)p)[i];
}
__device__ __forceinline__ float sigm(float x) { return 1.0f / (1.0f + __expf(-x)); }

// ---------------- dtype detection (int32 vs int64 indices) ------------------
// batch is sorted, values in [0,1024). If int64 (little-endian), every odd
// 32-bit word is a zero high-word. If int32, odd words are real batch values,
// many of which are nonzero within the first 20000 entries.
__global__ void detect_kernel(const void* batch, int N) {
    __shared__ int nz;
    if (threadIdx.x == 0) nz = 0;
    __syncthreads();
    int limit = N < 20000 ? N : 20000;
    int cnt = 0;
    for (int i = 1 + 2 * (int)threadIdx.x; i < limit; i += 2 * blockDim.x)
        if (((const int*)batch)[i] != 0) cnt++;
    if (cnt) atomicAdd(&nz, cnt);
    __syncthreads();
    if (threadIdx.x == 0) g_is64 = (nz == 0) ? 1 : 0;
}

// ---------------- zero LSTM state + q_star ----------------------------------
__global__ void init_kernel() {
    int i = blockIdx.x * blockDim.x + threadIdx.x;
    if (i < NGRAPH * DIM) { g_hs[i] = 0.0f; g_cs[i] = 0.0f; }
    if (i < NGRAPH * 2 * DIM) g_qstar[i] = 0.0f;
}

// ---------------- per-graph node ranges from sorted batch --------------------
__global__ void offsets_kernel(const void* batch, int N) {
    int n = blockIdx.x * blockDim.x + threadIdx.x;
    if (n >= N) return;
    int is64 = g_is64;
    int b = (int)ld_idx(batch, n, is64);
    if (n == 0) {
        for (int g = 0; g <= b; g++) g_start[g] = 0;
    } else {
        int prev = (int)ld_idx(batch, n - 1, is64);
        if (prev != b)
            for (int g = prev + 1; g <= b; g++) g_start[g] = n;
    }
    if (n == N - 1)
        for (int g = b + 1; g <= NGRAPH; g++) g_start[g] = N;
}

// ---------------- h0 = relu(x @ lin0_W + b); aggr initialized to h0 ---------
__global__ void lin0_kernel(const float* __restrict__ x,
                            const float* __restrict__ W,
                            const float* __restrict__ b, int N) {
    __shared__ float sW[INDIM * DIM];   // 25*64
    __shared__ float sx[4][INDIM];
    int tid = threadIdx.x;
    for (int i = tid; i < INDIM * DIM; i += blockDim.x) sW[i] = W[i];
    int node0 = blockIdx.x * 4;
    for (int i = tid; i < 4 * INDIM; i += blockDim.x) {
        int nl = i / INDIM, k = i % INDIM;
        int n = node0 + nl;
        sx[nl][k] = (n < N) ? x[(long long)n * INDIM + k] : 0.0f;
    }
    __syncthreads();
    int nl = tid >> 6;          // 0..3
    int c = tid & 63;
    int n = node0 + nl;
    if (n >= N) return;
    float acc = b[c];
#pragma unroll
    for (int k = 0; k < INDIM; k++) acc += sx[nl][k] * sW[k * DIM + c];
    acc = fmaxf(acc, 0.0f);
    long long o = (long long)n * DIM + c;
    g_h0[o] = acc;
    g_aggr[o] = acc;
}

// ---------------- edge scatter: aggr[dst] += h0[src] (vector red) -----------
__global__ void scatter_kernel(const void* __restrict__ edge, long long E) {
    long long t = (long long)blockIdx.x * blockDim.x + threadIdx.x;
    long long total = E * 16;
    if (t >= total) return;
    int is64 = g_is64;
    long long e = t >> 4;
    int q = (int)(t & 15);
    long long s = ld_idx(edge, e, is64);
    long long d = ld_idx(edge, E + e, is64);
    float4 v = *(const float4*)&g_h0[s * DIM + q * 4];
    float* dst = &g_aggr[d * DIM + q * 4];
    unsigned long long gaddr = (unsigned long long)__cvta_generic_to_global(dst);
    asm volatile("red.global.add.v4.f32 [%0], {%1, %2, %3, %4};"
                 :: "l"(gaddr), "f"(v.x), "f"(v.y), "f"(v.z), "f"(v.w)
                 : "memory");
}

// ---------------- h1 = relu(aggr @ gin_W + gin_b) ---------------------------
__global__ void gin_kernel(const float* __restrict__ W,
                           const float* __restrict__ b, int N) {
    __shared__ float sW[DIM * DIM];     // 16 KB
    __shared__ float srow[4][DIM];
    int tid = threadIdx.x;
    for (int i = tid; i < DIM * DIM; i += blockDim.x) sW[i] = W[i];
    int node0 = blockIdx.x * 4;
    for (int i = tid; i < 4 * DIM; i += blockDim.x) {
        int nl = i >> 6, k = i & 63;
        int n = node0 + nl;
        srow[nl][k] = (n < N) ? g_aggr[(long long)n * DIM + k] : 0.0f;
    }
    __syncthreads();
    int nl = tid >> 6;
    int c = tid & 63;
    int n = node0 + nl;
    if (n >= N) return;
    float acc = b[c];
#pragma unroll
    for (int k = 0; k < DIM; k++) acc += srow[nl][k] * sW[k * DIM + c];
    g_h1[(long long)n * DIM + c] = fmaxf(acc, 0.0f);
}

// ---------------- LSTM cell over 16 graphs per block -------------------------
__global__ void lstm_kernel(const float* __restrict__ W_ih,
                            const float* __restrict__ W_hh,
                            const float* __restrict__ b_ih,
                            const float* __restrict__ b_hh) {
    __shared__ float s[16 * 192];       // [g][0:128)=q_star, [128:192)=h
    __shared__ float gates[16 * 256];
    int tid = threadIdx.x;
    int gb = blockIdx.x * 16;
    for (int i = tid; i < 16 * 192; i += blockDim.x) {
        int g = i / 192, k = i % 192;
        s[i] = (k < 128) ? g_qstar[(gb + g) * 128 + k]
                         : g_hs[(gb + g) * 64 + (k - 128)];
    }
    __syncthreads();
    int r = tid;                        // gate row 0..255
    float acc[16];
    float bsum = b_ih[r] + b_hh[r];
#pragma unroll
    for (int g = 0; g < 16; g++) acc[g] = bsum;
    const float* wi = &W_ih[r * 128];
    for (int k = 0; k < 128; k++) {
        float w = wi[k];
#pragma unroll
        for (int g = 0; g < 16; g++) acc[g] += w * s[g * 192 + k];
    }
    const float* wh = &W_hh[r * 64];
    for (int k = 0; k < 64; k++) {
        float w = wh[k];
#pragma unroll
        for (int g = 0; g < 16; g++) acc[g] += w * s[g * 192 + 128 + k];
    }
#pragma unroll
    for (int g = 0; g < 16; g++) gates[g * 256 + r] = acc[g];
    __syncthreads();
    for (int cell = tid; cell < 16 * 64; cell += blockDim.x) {
        int g = cell >> 6, u = cell & 63;
        int gg = gb + g;
        float iv = gates[g * 256 + u];
        float fv = gates[g * 256 + 64 + u];
        float gv = gates[g * 256 + 128 + u];
        float ov = gates[g * 256 + 192 + u];
        float c_old = g_cs[gg * 64 + u];
        float c_new = sigm(fv) * c_old + sigm(iv) * tanhf(gv);
        float h_new = sigm(ov) * tanhf(c_new);
        g_cs[gg * 64 + u] = c_new;
        g_hs[gg * 64 + u] = h_new;
        g_qstar[gg * 128 + u] = h_new;   // q part of next q_star
    }
}

// ---------------- per-graph softmax attention + readout r -------------------
__global__ void attn_kernel() {
    __shared__ float qsh[DIM];
    __shared__ float rsh[4][DIM];
    __shared__ float dsh[4];
    __shared__ float msh[4];
    int g = blockIdx.x;
    int tid = threadIdx.x;
    int warp = tid >> 5, lane = tid & 31;
    if (tid < DIM) qsh[tid] = g_hs[g * DIM + tid];
    __syncthreads();
    int s0 = g_start[g], s1 = g_start[g + 1];
    // pass A: e[n] = <h1[n], q>, track max
    float lmax = -1e30f;
    float qa = qsh[2 * lane], qb = qsh[2 * lane + 1];
    for (int n = s0 + warp; n < s1; n += 4) {
        float2 hv = *(const float2*)&g_h1[(long long)n * DIM + 2 * lane];
        float p = hv.x * qa + hv.y * qb;
#pragma unroll
        for (int off = 16; off > 0; off >>= 1) p += __shfl_xor_sync(0xFFFFFFFF, p, off);
        if (lane == 0) g_e[n] = p;
        lmax = fmaxf(lmax, p);
    }
    if (lane == 0) msh[warp] = lmax;
    __syncthreads();
    float bmax = fmaxf(fmaxf(msh[0], msh[1]), fmaxf(msh[2], msh[3]));
    // pass B: softmax-weighted sum
    float dsum = 0.0f;
    float rx = 0.0f, ry = 0.0f;
    for (int n = s0 + warp; n < s1; n += 4) {
        float w = __expf(g_e[n] - bmax);
        float2 hv = *(const float2*)&g_h1[(long long)n * DIM + 2 * lane];
        rx += w * hv.x;
        ry += w * hv.y;
        dsum += w;
    }
    rsh[warp][2 * lane] = rx;
    rsh[warp][2 * lane + 1] = ry;
    if (lane == 0) dsh[warp] = dsum;
    __syncthreads();
    if (tid < DIM) {
        float r = rsh[0][tid] + rsh[1][tid] + rsh[2][tid] + rsh[3][tid];
        float den = dsh[0] + dsh[1] + dsh[2] + dsh[3];
        if (den == 0.0f) den = 1.0f;
        g_qstar[g * 128 + DIM + tid] = r / den;
    }
}

// ---------------- head: out = relu(q_star@lin1+b1) @ lin2 + b2 --------------
__global__ void head_kernel(const float* __restrict__ lin1_W,
                            const float* __restrict__ lin1_b,
                            const float* __restrict__ lin2_W,
                            const float* __restrict__ lin2_b,
                            float* __restrict__ out) {
    __shared__ float qs[128];
    __shared__ float red[64];
    int g = blockIdx.x;
    int t = threadIdx.x;
    qs[t] = g_qstar[g * 128 + t];
    qs[t + 64] = g_qstar[g * 128 + t + 64];
    __syncthreads();
    float acc = lin1_b[t];
#pragma unroll 8
    for (int k = 0; k < 128; k++) acc += qs[k] * lin1_W[k * 64 + t];
    acc = fmaxf(acc, 0.0f);
    red[t] = acc * lin2_W[t];
    __syncthreads();
    if (t < 32) {
        float v = red[t] + red[t + 32];
#pragma unroll
        for (int off = 16; off > 0; off >>= 1) v += __shfl_xor_sync(0xFFFFFFFF, v, off);
        if (t == 0) out[g] = v + lin2_b[0];
    }
}

// ---------------- launch ------------------------------------------------------
extern "C" void kernel_launch(void* const* d_in, const int* in_sizes, int n_in,
                              void* d_out, int out_size) {
    const float* x      = (const float*)d_in[0];
    const void*  edge   = d_in[1];
    const void*  batch  = d_in[2];
    const float* lin0_W = (const float*)d_in[3];
    const float* lin0_b = (const float*)d_in[4];
    const float* gin_W  = (const float*)d_in[5];
    const float* gin_b  = (const float*)d_in[6];
    const float* W_ih   = (const float*)d_in[7];
    const float* W_hh   = (const float*)d_in[8];
    const float* b_ih   = (const float*)d_in[9];
    const float* b_hh   = (const float*)d_in[10];
    const float* lin1_W = (const float*)d_in[11];
    const float* lin1_b = (const float*)d_in[12];
    const float* lin2_W = (const float*)d_in[13];
    const float* lin2_b = (const float*)d_in[14];
    float* out = (float*)d_out;

    int N = in_sizes[0] / INDIM;
    long long E = (long long)in_sizes[1] / 2;

    detect_kernel<<<1, 256>>>(batch, N);
    init_kernel<<<(NGRAPH * 2 * DIM + 255) / 256, 256>>>();
    offsets_kernel<<<(N + 255) / 256, 256>>>(batch, N);
    lin0_kernel<<<(N + 3) / 4, 256>>>(x, lin0_W, lin0_b, N);
    long long sc_threads = E * 16;
    scatter_kernel<<<(unsigned)((sc_threads + 255) / 256), 256>>>(edge, E);
    gin_kernel<<<(N + 3) / 4, 256>>>(gin_W, gin_b, N);
    for (int step = 0; step < 3; step++) {
        lstm_kernel<<<NGRAPH / 16, 256>>>(W_ih, W_hh, b_ih, b_hh);
        attn_kernel<<<NGRAPH, 128>>>();
    }
    head_kernel<<<NGRAPH, 64>>>(lin1_W, lin1_b, lin2_W, lin2_b, out);
}